// round 7
// baseline (speedup 1.0000x reference)
#include <cuda_runtime.h>
#include <math.h>

#define Nn 100000
#define Ee 3200000
#define Fin 256

// ---------------- scratch (device globals; no allocations allowed) ----------
__device__ float g_dinv[Nn];
__device__ int   g_deg[Nn];
__device__ float g_h1[(size_t)Nn * 32];    // x @ init_w1   (layer1, both stacks)
__device__ float g_r1[(size_t)Nn * 32];    // x @ root_w1
__device__ float g_agg1[(size_t)Nn * 32];  // scatter accumulator layer1
__device__ float g_h2[(size_t)Nn * 32];    // h @ init_w2
__device__ float g_r2[(size_t)Nn * 32];    // h @ root_w2
__device__ float g_agg2[(size_t)Nn * 32];  // scatter accumulator layer2

// ---------------- zero scratch (graph-replayed every iteration) -------------
__global__ void k_zero() {
    size_t i = (size_t)blockIdx.x * blockDim.x + threadIdx.x;
    size_t stride = (size_t)gridDim.x * blockDim.x;
    const size_t na = (size_t)Nn * 32;
    for (size_t j = i; j < na; j += stride) {
        g_agg1[j] = 0.0f;
        g_agg2[j] = 0.0f;
    }
    for (size_t j = i; j < Nn; j += stride) g_deg[j] = 0;
}

// ---------------- degree / norm ---------------------------------------------
// edge_index is int32 (JAX x64 disabled): layout [2, E] -> src = ei[e], dst = ei[E+e]
__global__ void k_deg(const int* __restrict__ ei) {
    int e = blockIdx.x * blockDim.x + threadIdx.x;
    if (e < Ee) {
        unsigned d = (unsigned)ei[Ee + e];
        if (d < Nn) atomicAdd(&g_deg[d], 1);
    }
}

__global__ void k_dinv() {
    int i = blockIdx.x * blockDim.x + threadIdx.x;
    if (i < Nn) {
        int d = g_deg[i];
        g_dinv[i] = (d > 0) ? rsqrtf((float)d) : 0.0f;
    }
}

// ---------------- GEMM1: x[N,256] -> h1[N,32], r1[N,32] ---------------------
// Register-tiled: 64 nodes x 64 outputs per block (cols 0..31 = init, 32..63 = root),
// 256 threads, 4x4 accumulators per thread, K-chunk 32, float4 smem reads.
__global__ __launch_bounds__(256) void k_gemm1(const float* __restrict__ x,
                                               const float* __restrict__ iw,
                                               const float* __restrict__ rw) {
    __shared__ __align__(16) float xs[32][68];  // [k][node], pad 68 keeps 16B row align
    __shared__ __align__(16) float ws[32][64];  // [k][out]

    int n0 = blockIdx.x * 64;
    int t = threadIdx.x;
    int node4 = (t & 15) * 4;   // 0..60
    int out4  = (t >> 4) * 4;   // 0..60

    float acc[4][4] = {};

    for (int kk = 0; kk < Fin; kk += 32) {
        // load x tile (transposed into smem)
        int nl = t >> 5;        // 0..7
        int kl = t & 31;        // 0..31
        #pragma unroll
        for (int r = 0; r < 8; r++) {
            int node = n0 + nl + r * 8;
            xs[kl][nl + r * 8] = (node < Nn) ? x[(size_t)node * Fin + kk + kl] : 0.0f;
        }
        // load weight tile: 32k x 64out
        #pragma unroll
        for (int r = 0; r < 8; r++) {
            int j = t + r * 256;
            int kw = j >> 6;    // 0..31
            int c  = j & 63;    // 0..63
            int cc = c & 31;
            const float* wsrc = (c < 32) ? iw : rw;
            // weight layout [K=2][256][16]: (k,f,o) -> k*4096 + f*16 + o
            ws[kw][c] = wsrc[(cc >> 4) * 4096 + (kk + kw) * 16 + (cc & 15)];
        }
        __syncthreads();

        #pragma unroll
        for (int k = 0; k < 32; k++) {
            float4 xv = *(const float4*)&xs[k][node4];
            float4 wv = *(const float4*)&ws[k][out4];
            float xa[4] = {xv.x, xv.y, xv.z, xv.w};
            float wa[4] = {wv.x, wv.y, wv.z, wv.w};
            #pragma unroll
            for (int i = 0; i < 4; i++)
                #pragma unroll
                for (int j = 0; j < 4; j++)
                    acc[i][j] += xa[i] * wa[j];
        }
        __syncthreads();
    }

    #pragma unroll
    for (int i = 0; i < 4; i++) {
        int node = n0 + node4 + i;
        if (node >= Nn) continue;
        #pragma unroll
        for (int j = 0; j < 4; j++) {
            int c = out4 + j;
            if (c < 32) g_h1[(size_t)node * 32 + c] = acc[i][j];
            else        g_r1[(size_t)node * 32 + (c - 32)] = acc[i][j];
        }
    }
}

// ---------------- edge scatter: warp per edge, lane per feature -------------
template <int LAYER>
__global__ __launch_bounds__(256) void k_edge(const int* __restrict__ ei) {
    unsigned tid = blockIdx.x * 256u + threadIdx.x;
    unsigned e = tid >> 5;
    if (e >= Ee) return;
    int lane = threadIdx.x & 31;
    unsigned s = (unsigned)__ldg(&ei[e]);
    unsigned d = (unsigned)__ldg(&ei[Ee + e]);
    if (s >= Nn || d >= Nn) return;
    float nrm = g_dinv[s] * g_dinv[d];
    const float* h   = (LAYER == 1) ? g_h1 : g_h2;
    float*       agg = (LAYER == 1) ? g_agg1 : g_agg2;
    float v = h[(size_t)s * 32 + lane] * nrm;
    atomicAdd(&agg[(size_t)d * 32 + lane], v);
}

// ---------------- combine layer1 + tiny GEMM2 (warp per node) ---------------
// h[n,o] = mean_k relu(agg1 + r1 + b1)   (outer relu is identity: mean of relus >= 0)
// then h2 = h @ init_w2, r2 = h @ root_w2  (16x16 per stack, via warp shuffles)
__global__ __launch_bounds__(256) void k_combine1(const float* __restrict__ b1,
                                                  const float* __restrict__ iw2,
                                                  const float* __restrict__ rw2,
                                                  float* __restrict__ outAgg) {
    unsigned n = (blockIdx.x * 256u + threadIdx.x) >> 5;
    if (n >= Nn) return;
    int lane = threadIdx.x & 31;
    size_t idx = (size_t)n * 32 + lane;

    float v = g_agg1[idx] + g_r1[idx] + b1[lane];
    v = fmaxf(v, 0.0f);
    // lane = k*16 + o ; pair-mean across stacks -> every lane holds h[o = lane&15]
    float h = 0.5f * (v + __shfl_xor_sync(0xffffffffu, v, 16));

    if (lane < 16) outAgg[(size_t)n * 16 + lane] = h;  // agg_feature output

    // out idx = lane: k = lane>>4, o = lane&15 ; weights [2][16][16]
    int base = (lane >> 4) * 256 + (lane & 15);
    float ai = 0.0f, ar = 0.0f;
    #pragma unroll
    for (int f = 0; f < 16; f++) {
        float hf = __shfl_sync(0xffffffffu, h, f);
        ai += hf * iw2[base + f * 16];
        ar += hf * rw2[base + f * 16];
    }
    g_h2[idx] = ai;
    g_r2[idx] = ar;
}

// ---------------- final: logits + log_softmax (warp per node) ---------------
__global__ __launch_bounds__(256) void k_final(const float* __restrict__ b2,
                                               float* __restrict__ out) {
    unsigned n = (blockIdx.x * 256u + threadIdx.x) >> 5;
    if (n >= Nn) return;
    int lane = threadIdx.x & 31;
    size_t idx = (size_t)n * 32 + lane;

    float v = g_agg2[idx] + g_r2[idx] + b2[lane];
    // mean over K stacks -> lane l and l^16 now hold identical logit[o=l&15]
    v = 0.5f * (v + __shfl_xor_sync(0xffffffffu, v, 16));

    float m = v;
    #pragma unroll
    for (int o = 8; o; o >>= 1) m = fmaxf(m, __shfl_xor_sync(0xffffffffu, m, o));
    float e = expf(v - m);
    float s = e;
    #pragma unroll
    for (int o = 8; o; o >>= 1) s += __shfl_xor_sync(0xffffffffu, s, o);
    float r = v - m - logf(s);

    if (lane < 16) out[(size_t)n * 16 + lane] = r;
}

// ---------------- launch ------------------------------------------------------
extern "C" void kernel_launch(void* const* d_in, const int* in_sizes, int n_in,
                              void* d_out, int out_size) {
    const float* x   = (const float*)d_in[0];
    const int*   ei  = (const int*)d_in[1];      // int32 edge_index [2, E]
    const float* iw1 = (const float*)d_in[2];
    const float* rw1 = (const float*)d_in[3];
    const float* b1  = (const float*)d_in[4];
    const float* iw2 = (const float*)d_in[5];
    const float* rw2 = (const float*)d_in[6];
    const float* b2  = (const float*)d_in[7];
    float* out = (float*)d_out;

    k_zero<<<592, 256>>>();   // 592*256 ~= 148 SMs * 1024 threads

    k_deg<<<(Ee + 255) / 256, 256>>>(ei);
    k_dinv<<<(Nn + 255) / 256, 256>>>();
    k_gemm1<<<(Nn + 63) / 64, 256>>>(x, iw1, rw1);

    unsigned edge_blocks = (unsigned)(((size_t)Ee * 32 + 255) / 256);
    k_edge<1><<<edge_blocks, 256>>>(ei);

    unsigned node_warp_blocks = (Nn * 32 + 255) / 256;
    k_combine1<<<node_warp_blocks, 256>>>(b1, iw2, rw2, out + (size_t)Nn * 16);

    k_edge<2><<<edge_blocks, 256>>>(ei);

    k_final<<<node_warp_blocks, 256>>>(b2, out);
}

// round 10
// speedup vs baseline: 2.1219x; 2.1219x over previous
#include <cuda_runtime.h>
#include <math.h>

#define Nn 100000
#define Ee 3200000
#define Fin 256

// ---------------- scratch (device globals; no allocations allowed) ----------
__device__ float  g_dinv[Nn];
__device__ int    g_deg[Nn];
__device__ float4 g_h1[(size_t)Nn * 8];    // x @ init_w1 / root stacked: [n][32] viewed as [n][8] float4
__device__ float4 g_r1[(size_t)Nn * 8];
__device__ float4 g_agg1[(size_t)Nn * 8];
__device__ float4 g_h2[(size_t)Nn * 8];
__device__ float4 g_r2[(size_t)Nn * 8];
__device__ float4 g_agg2[(size_t)Nn * 8];

// ---------------- zero scratch (graph-replayed every iteration) -------------
__global__ void k_zero() {
    size_t i = (size_t)blockIdx.x * blockDim.x + threadIdx.x;
    size_t stride = (size_t)gridDim.x * blockDim.x;
    const size_t na = (size_t)Nn * 8;
    float4 z = make_float4(0.f, 0.f, 0.f, 0.f);
    for (size_t j = i; j < na; j += stride) {
        g_agg1[j] = z;
        g_agg2[j] = z;
    }
    for (size_t j = i; j < Nn; j += stride) g_deg[j] = 0;
}

// ---------------- degree / norm ---------------------------------------------
// edge_index is int32: layout [2, E] -> src = ei[e], dst = ei[E+e]
__global__ void k_deg(const int* __restrict__ ei) {
    int e = blockIdx.x * blockDim.x + threadIdx.x;
    if (e < Ee) {
        unsigned d = (unsigned)ei[Ee + e];
        if (d < Nn) atomicAdd(&g_deg[d], 1);
    }
}

__global__ void k_dinv() {
    int i = blockIdx.x * blockDim.x + threadIdx.x;
    if (i < Nn) {
        int d = g_deg[i];
        g_dinv[i] = (d > 0) ? rsqrtf((float)d) : 0.0f;
    }
}

// ---------------- GEMM1: x[N,256] -> h1[N,32], r1[N,32] ---------------------
// 128 nodes x 64 outputs per block (cols 0..31 = init stacks, 32..63 = root),
// 256 threads, 8x4 accumulators per thread, K-chunk 32, float4 smem reads.
__global__ __launch_bounds__(256) void k_gemm1(const float* __restrict__ x,
                                               const float* __restrict__ iw,
                                               const float* __restrict__ rw) {
    __shared__ __align__(16) float xs[32][132];  // [k][node], 132*4=528B rows (16B aligned)
    __shared__ __align__(16) float ws[32][64];   // [k][out]

    int n0 = blockIdx.x * 128;
    int t = threadIdx.x;
    int out4  = (t & 15) * 4;   // 0..60
    int node8 = (t >> 4) * 8;   // 0..120

    float acc[8][4] = {};

    for (int kk = 0; kk < Fin; kk += 32) {
        // x tile: 128 nodes x 32 k, transposed into smem
        int nl = t >> 5;        // 0..7
        int kl = t & 31;        // 0..31
        #pragma unroll
        for (int r = 0; r < 16; r++) {
            int node = n0 + nl + r * 8;
            xs[kl][nl + r * 8] = (node < Nn) ? x[(size_t)node * Fin + kk + kl] : 0.0f;
        }
        // weight tile: 32k x 64out ; weight layout [K=2][256][16]
        #pragma unroll
        for (int r = 0; r < 8; r++) {
            int j = t + r * 256;
            int kw = j >> 6;    // 0..31
            int c  = j & 63;    // 0..63
            int cc = c & 31;
            const float* wsrc = (c < 32) ? iw : rw;
            ws[kw][c] = wsrc[(cc >> 4) * 4096 + (kk + kw) * 16 + (cc & 15)];
        }
        __syncthreads();

        #pragma unroll
        for (int k = 0; k < 32; k++) {
            float4 a0 = *(const float4*)&xs[k][node8];
            float4 a1 = *(const float4*)&xs[k][node8 + 4];
            float4 w4 = *(const float4*)&ws[k][out4];
            float xa[8] = {a0.x, a0.y, a0.z, a0.w, a1.x, a1.y, a1.z, a1.w};
            float wa[4] = {w4.x, w4.y, w4.z, w4.w};
            #pragma unroll
            for (int i = 0; i < 8; i++)
                #pragma unroll
                for (int j = 0; j < 4; j++)
                    acc[i][j] += xa[i] * wa[j];
        }
        __syncthreads();
    }

    float* h1 = (float*)g_h1;
    float* r1 = (float*)g_r1;
    #pragma unroll
    for (int i = 0; i < 8; i++) {
        int node = n0 + node8 + i;
        if (node >= Nn) continue;
        #pragma unroll
        for (int j = 0; j < 4; j++) {
            int c = out4 + j;
            if (c < 32) h1[(size_t)node * 32 + c] = acc[i][j];
            else        r1[(size_t)node * 32 + (c - 32)] = acc[i][j];
        }
    }
}

// ---------------- edge scatter: 8 lanes per edge, float4 per lane -----------
// Each lane: one 16B gather + one red.global.add.v4.f32 (no-return vector atomic).
template <int LAYER>
__global__ __launch_bounds__(256) void k_edge(const int* __restrict__ ei) {
    unsigned tid = blockIdx.x * 256u + threadIdx.x;
    unsigned e   = tid >> 3;          // 8 lanes per edge
    if (e >= Ee) return;
    unsigned sub = tid & 7;

    unsigned s = (unsigned)__ldg(&ei[e]);
    unsigned d = (unsigned)__ldg(&ei[Ee + e]);
    if (s >= Nn || d >= Nn) return;
    float nrm = g_dinv[s] * g_dinv[d];

    const float4* h   = (LAYER == 1) ? g_h1 : g_h2;
    float4*       agg = (LAYER == 1) ? g_agg1 : g_agg2;

    float4 v = __ldg(&h[(size_t)s * 8 + sub]);
    v.x *= nrm; v.y *= nrm; v.z *= nrm; v.w *= nrm;
    float4* dst = &agg[(size_t)d * 8 + sub];
    asm volatile("red.global.add.v4.f32 [%0], {%1, %2, %3, %4};"
                 :: "l"(dst), "f"(v.x), "f"(v.y), "f"(v.z), "f"(v.w)
                 : "memory");
}

// ---------------- combine layer1 + tiny GEMM2 (warp per node) ---------------
// h[n,o] = mean_k relu(agg1 + r1 + b1)   (outer relu is identity: mean of relus >= 0)
// then h2 = h @ init_w2, r2 = h @ root_w2  (16x16 per stack, via warp shuffles)
__global__ __launch_bounds__(256) void k_combine1(const float* __restrict__ b1,
                                                  const float* __restrict__ iw2,
                                                  const float* __restrict__ rw2,
                                                  float* __restrict__ outAgg) {
    unsigned n = (blockIdx.x * 256u + threadIdx.x) >> 5;
    if (n >= Nn) return;
    int lane = threadIdx.x & 31;
    size_t idx = (size_t)n * 32 + lane;

    const float* agg1 = (const float*)g_agg1;
    const float* r1   = (const float*)g_r1;
    float v = agg1[idx] + r1[idx] + b1[lane];
    v = fmaxf(v, 0.0f);
    // lane = k*16 + o ; pair-mean across stacks -> every lane holds h[o = lane&15]
    float h = 0.5f * (v + __shfl_xor_sync(0xffffffffu, v, 16));

    if (lane < 16) outAgg[(size_t)n * 16 + lane] = h;  // agg_feature output

    // out idx = lane: k = lane>>4, o = lane&15 ; weights [2][16][16]
    int base = (lane >> 4) * 256 + (lane & 15);
    float ai = 0.0f, ar = 0.0f;
    #pragma unroll
    for (int f = 0; f < 16; f++) {
        float hf = __shfl_sync(0xffffffffu, h, f);
        ai += hf * iw2[base + f * 16];
        ar += hf * rw2[base + f * 16];
    }
    ((float*)g_h2)[idx] = ai;
    ((float*)g_r2)[idx] = ar;
}

// ---------------- final: logits + log_softmax (warp per node) ---------------
__global__ __launch_bounds__(256) void k_final(const float* __restrict__ b2,
                                               float* __restrict__ out) {
    unsigned n = (blockIdx.x * 256u + threadIdx.x) >> 5;
    if (n >= Nn) return;
    int lane = threadIdx.x & 31;
    size_t idx = (size_t)n * 32 + lane;

    const float* agg2 = (const float*)g_agg2;
    const float* r2   = (const float*)g_r2;
    float v = agg2[idx] + r2[idx] + b2[lane];
    // mean over K stacks -> lane l and l^16 now hold identical logit[o=l&15]
    v = 0.5f * (v + __shfl_xor_sync(0xffffffffu, v, 16));

    float m = v;
    #pragma unroll
    for (int o = 8; o; o >>= 1) m = fmaxf(m, __shfl_xor_sync(0xffffffffu, m, o));
    float e = expf(v - m);
    float s = e;
    #pragma unroll
    for (int o = 8; o; o >>= 1) s += __shfl_xor_sync(0xffffffffu, s, o);
    float r = v - m - logf(s);

    if (lane < 16) out[(size_t)n * 16 + lane] = r;
}

// ---------------- launch ------------------------------------------------------
extern "C" void kernel_launch(void* const* d_in, const int* in_sizes, int n_in,
                              void* d_out, int out_size) {
    const float* x   = (const float*)d_in[0];
    const int*   ei  = (const int*)d_in[1];      // int32 edge_index [2, E]
    const float* iw1 = (const float*)d_in[2];
    const float* rw1 = (const float*)d_in[3];
    const float* b1  = (const float*)d_in[4];
    const float* iw2 = (const float*)d_in[5];
    const float* rw2 = (const float*)d_in[6];
    const float* b2  = (const float*)d_in[7];
    float* out = (float*)d_out;

    k_zero<<<592, 256>>>();

    k_deg<<<(Ee + 255) / 256, 256>>>(ei);
    k_dinv<<<(Nn + 255) / 256, 256>>>();
    k_gemm1<<<(Nn + 127) / 128, 256>>>(x, iw1, rw1);

    unsigned edge_blocks = (unsigned)(((size_t)Ee * 8 + 255) / 256);  // 8 lanes/edge
    k_edge<1><<<edge_blocks, 256>>>(ei);

    unsigned node_warp_blocks = (Nn * 32 + 255) / 256;
    k_combine1<<<node_warp_blocks, 256>>>(b1, iw2, rw2, out + (size_t)Nn * 16);

    k_edge<2><<<edge_blocks, 256>>>(ei);

    k_final<<<node_warp_blocks, 256>>>(b2, out);
}